// round 15
// baseline (speedup 1.0000x reference)
#include <cuda_runtime.h>
#include <cuda_fp16.h>

#define Bn 4096
#define Sn 64
#define Un 128
#define Mn 32
#define NUNF 6
#define EPSF 1e-8f
#define NPAIR 7
#define NWARP (2*NPAIR)
#define NTHR (NWARP*32)

__device__ __forceinline__ float ftanh(float x) {
    float t; asm("tanh.approx.f32 %0, %1;" : "=f"(t) : "f"(x));
    return t;
}
__device__ __forceinline__ void barpair(int pid) {
    asm volatile("bar.sync %0, 64;" :: "r"(pid + 1) : "memory");
}
// src index embedded in low 7 mantissa bits of fp32 w (w used unstripped in
// accumulation: <= 2^-16 relative perturbation, below fp16 noise)
__device__ __forceinline__ int widx(float wv) {
    return (int)(__float_as_uint(wv) & 0x7Fu);
}
__device__ __forceinline__ unsigned packh2(float a, float b) {
    __half2 h = __floats2half2_rn(a, b);
    return *(unsigned*)&h;
}
__device__ __forceinline__ __half2 u2h(unsigned u) { return *(__half2*)&u; }

// one (entry, comp) for 4 batches: AH/BH splat-half2 params, G = half4 gather
#define MATHT(AH,BH,G,WJ,F) { \
    __half2 r01 = __hfma2(u2h(AH), u2h(G.x), u2h(BH)); \
    __half2 r23 = __hfma2(u2h(AH), u2h(G.y), u2h(BH)); \
    float2 f01 = __half22float2(r01), f23 = __half22float2(r23); \
    float wa = fabsf(WJ); float t; \
    t = ftanh(f01.x); mN0.F = fmaf(t,WJ,mN0.F); mD0.F = fmaf(t,wa,mD0.F); \
    t = ftanh(f01.y); mN1.F = fmaf(t,WJ,mN1.F); mD1.F = fmaf(t,wa,mD1.F); \
    t = ftanh(f23.x); mN2.F = fmaf(t,WJ,mN2.F); mD2.F = fmaf(t,wa,mD2.F); \
    t = ftanh(f23.y); mN3.F = fmaf(t,WJ,mN3.F); mD3.F = fmaf(t,wa,mD3.F); }

// Fused LTC kernel. 148 CTAs x 448 threads (7 warp pairs, 4 batches/pair).
// Per-dst compacted synapses (50% masks). a,b stored as splat-half2 planes
// (args computed with HFMA2 directly on fp16 v/x); w fp32 with embedded idx;
// v and x broadcast tables stored as half4 (uint2). tanh + accumulation fp32.
__global__ __launch_bounds__(NTHR, 1) void ltc_all(
    const float* __restrict__ inputs, const float* __restrict__ state,
    const float* __restrict__ gleak,  const float* __restrict__ vleak,
    const float* __restrict__ cm,
    const float* __restrict__ sigma,  const float* __restrict__ mu,
    const float* __restrict__ w,      const float* __restrict__ erev,
    const float* __restrict__ ssig,   const float* __restrict__ smu,
    const float* __restrict__ sw,     const float* __restrict__ serev,
    const float* __restrict__ mask,   const float* __restrict__ smask,
    const float* __restrict__ inw,    const float* __restrict__ inb,
    const float* __restrict__ outw,   const float* __restrict__ outb,
    float* __restrict__ dout)
{
    extern __shared__ float sm[];
    unsigned* sAh = (unsigned*)sm;           // Un*Un: splat-half2 a
    unsigned* sBh = (unsigned*)(sm + Un*Un); // Un*Un: splat-half2 b
    float*    sWf = sm + 2*Un*Un;            // Un*Un: w fp32 (idx embedded on compaction)
    float*    sVq = sm + 3*Un*Un;            // NPAIR*512: v as half4 (uint2) per src
    float*    sXc = sVq + NPAIR*512;         // NPAIR*512: xq (half4) / exchange
    float*    sNB = sXc + NPAIR*512;         // Un nbase
    float*    sDB = sNB + Un;                // Un dbase
    int*      sL  = (int*)(sDB + Un);        // [0]=recurrent L, [1]=sensory Ls

    int tid = threadIdx.x;
    if (tid == 0) { sL[0] = 0; sL[1] = 0; }

    // ---- A1: fold sensory params into SMEM (dense) ----
    {
        const float4* s4 = (const float4*)ssig;
        const float4* m4 = (const float4*)smu;
        const float4* w4 = (const float4*)sw;
        const float4* e4 = (const float4*)serev;
        const float4* k4 = (const float4*)smask;
        for (int i = tid; i < Sn*Un/4; i += NTHR) {
            float4 sg = s4[i], mm = m4[i], ww = w4[i], ee = e4[i], kk = k4[i];
            float ax = 0.5f*sg.x, ay = 0.5f*sg.y, az = 0.5f*sg.z, aw = 0.5f*sg.w;
            uint4 ah, bh;
            ah.x = packh2(ax, ax); ah.y = packh2(ay, ay);
            ah.z = packh2(az, az); ah.w = packh2(aw, aw);
            float bx = -ax*mm.x, by = -ay*mm.y, bz = -az*mm.z, bw = -aw*mm.w;
            bh.x = packh2(bx, bx); bh.y = packh2(by, by);
            bh.z = packh2(bz, bz); bh.w = packh2(bw, bw);
            float4 we;
            we.x = 0.5f*ww.x*kk.x*ee.x; we.y = 0.5f*ww.y*kk.y*ee.y;
            we.z = 0.5f*ww.z*kk.z*ee.z; we.w = 0.5f*ww.w*kk.w*ee.w;
            ((uint4*)sAh)[i] = ah; ((uint4*)sBh)[i] = bh; ((float4*)sWf)[i] = we;
        }
    }
    __syncthreads();

    int warp = tid >> 5, lane = tid & 31, d0 = lane * 4;
    int pid = warp % NPAIR;
    bool hi = (warp >= NPAIR);
    int start = (int)(((long long)blockIdx.x       * Bn) / gridDim.x);
    int end   = (int)(((long long)(blockIdx.x + 1) * Bn) / gridDim.x);
    int b0 = start + pid*4;
    int b1 = (b0+1 < end) ? b0+1 : end-1;
    int b2 = (b0+2 < end) ? b0+2 : end-1;
    int b3 = (b0+3 < end) ? b0+3 : end-1;
    unsigned* vqh = (unsigned*)(sVq + pid*512);   // 128 x uint2 (half4) per pair
    float* xch = sXc + pid*512;                   // xq (64 uint2) then exchange buffer

    float colSn = 0.f, colSd = 0.f;
    int cnt_s = 0;

    // ---- scan 1 (tid<128): sensory col-sums + in-place compaction ----
    if (tid < Un) {
        for (int s = 0; s < Sn; ++s) {
            float wv = sWf[s*Un + tid];
            colSn += wv; colSd += fabsf(wv);
            if (wv != 0.f) {
                sAh[cnt_s*Un + tid] = sAh[s*Un + tid];
                sBh[cnt_s*Un + tid] = sBh[s*Un + tid];
                sWf[cnt_s*Un + tid] =
                    __uint_as_float((__float_as_uint(wv) & 0xFFFFFF80u) | (unsigned)s);
                cnt_s++;
            }
        }
        atomicMax(&sL[1], cnt_s);
    }
    // ---- HIGH warps stage xq[s] = half4 (x_b0, x_b1, x_b2, x_b3) ----
    if (hi) {
        for (int s = lane; s < Sn; s += 32) {
            float iw_ = inw[s], ib_ = inb[s];
            float x0 = fmaf(inputs[b0*Sn + s], iw_, ib_);
            float x1 = fmaf(inputs[b1*Sn + s], iw_, ib_);
            float x2 = fmaf(inputs[b2*Sn + s], iw_, ib_);
            float x3 = fmaf(inputs[b3*Sn + s], iw_, ib_);
            uint2 xv; xv.x = packh2(x0, x1); xv.y = packh2(x2, x3);
            ((uint2*)xch)[s] = xv;
        }
    }
    __syncthreads();
    int Ls = sL[1];
    if (tid < Un) {   // pad sensory rows (w=0 -> exact zero contribution)
        for (int e = cnt_s; e < Ls; ++e) {
            sAh[e*Un + tid] = 0; sBh[e*Un + tid] = 0; sWf[e*Un + tid] = 0.f;
        }
    }
    __syncthreads();

    // ---- sensory gather loop (compacted, pair-split, half4 gathers) ----
    float4 mN0 = make_float4(0,0,0,0), mN1 = mN0, mN2 = mN0, mN3 = mN0;
    float4 mD0 = mN0, mD1 = mN0, mD2 = mN0, mD3 = mN0;
    {
        const uint4* A4 = (const uint4*)sAh;
        const uint4* B4 = (const uint4*)sBh;
        const float4* W4 = (const float4*)sWf;
        const uint2* xq2 = (const uint2*)xch;
        int Lsh  = (Ls + 1) >> 1;
        int eB = hi ? Lsh : 0;
        int eE = hi ? Ls  : Lsh;
        #pragma unroll 4
        for (int e = eB; e < eE; ++e) {
            uint4 ah = A4[e*32 + lane];
            uint4 bh = B4[e*32 + lane];
            float4 we = W4[e*32 + lane];
            uint2 gx = xq2[widx(we.x)], gy = xq2[widx(we.y)];
            uint2 gz = xq2[widx(we.z)], gw = xq2[widx(we.w)];
            MATHT(ah.x, bh.x, gx, we.x, x)
            MATHT(ah.y, bh.y, gy, we.y, y)
            MATHT(ah.z, bh.z, gz, we.z, z)
            MATHT(ah.w, bh.w, gw, we.w, w)
        }
    }
    float4 aN0 = mN0, aN1 = mN1, aN2 = mN2, aN3 = mN3;
    float4 aD0 = mD0, aD1 = mD1, aD2 = mD2, aD3 = mD3;
    __syncthreads();   // done reading sensory planes + xq

    // ---- A2: fold recurrent params into SMEM (dense, overwrite) ----
    {
        const float4* s4 = (const float4*)sigma;
        const float4* m4 = (const float4*)mu;
        const float4* w4 = (const float4*)w;
        const float4* e4 = (const float4*)erev;
        const float4* k4 = (const float4*)mask;
        for (int i = tid; i < Un*Un/4; i += NTHR) {
            float4 sg = s4[i], mm = m4[i], ww = w4[i], ee = e4[i], kk = k4[i];
            float ax = 0.5f*sg.x, ay = 0.5f*sg.y, az = 0.5f*sg.z, aw = 0.5f*sg.w;
            uint4 ah, bh;
            ah.x = packh2(ax, ax); ah.y = packh2(ay, ay);
            ah.z = packh2(az, az); ah.w = packh2(aw, aw);
            float bx = -ax*mm.x, by = -ay*mm.y, bz = -az*mm.z, bw = -aw*mm.w;
            bh.x = packh2(bx, bx); bh.y = packh2(by, by);
            bh.z = packh2(bz, bz); bh.w = packh2(bw, bw);
            float4 we;
            we.x = 0.5f*ww.x*kk.x*ee.x; we.y = 0.5f*ww.y*kk.y*ee.y;
            we.z = 0.5f*ww.z*kk.z*ee.z; we.w = 0.5f*ww.w*kk.w*ee.w;
            ((uint4*)sAh)[i] = ah; ((uint4*)sBh)[i] = bh; ((float4*)sWf)[i] = we;
        }
    }
    __syncthreads();

    // ---- scan 2 (tid<128): recurrent col-sums + compaction + base assembly ----
    int cnt = 0;
    if (tid < Un) {
        float n = colSn, d = colSd;
        for (int s = 0; s < Un; ++s) {
            float wv = sWf[s*Un + tid];
            n += wv; d += fabsf(wv);
            if (wv != 0.f) {
                sAh[cnt*Un + tid] = sAh[s*Un + tid];
                sBh[cnt*Un + tid] = sBh[s*Un + tid];
                sWf[cnt*Un + tid] =
                    __uint_as_float((__float_as_uint(wv) & 0xFFFFFF80u) | (unsigned)s);
                cnt++;
            }
        }
        atomicMax(&sL[0], cnt);
        float gl = gleak[tid];
        sNB[tid] = fmaf(gl, vleak[tid], n);
        sDB[tid] = cm[tid]*(float)NUNF + gl + EPSF + d;
    }
    __syncthreads();
    int L = sL[0];
    if (tid < Un) {
        for (int e = cnt; e < L; ++e) {
            sAh[e*Un + tid] = 0; sBh[e*Un + tid] = 0; sWf[e*Un + tid] = 0.f;
        }
    }
    __syncthreads();

    // ---- init constants; bases folded only into LOW warp's partials ----
    float4 cmt;
    {
        float4 cm4 = *(const float4*)(cm + d0);
        cmt.x = cm4.x*(float)NUNF; cmt.y = cm4.y*(float)NUNF;
        cmt.z = cm4.z*(float)NUNF; cmt.w = cm4.w*(float)NUNF;
        if (!hi) {
            float4 nb4 = *(const float4*)(sNB + d0);
            float4 db4 = *(const float4*)(sDB + d0);
            #define ADD4(T,S) T.x += S.x; T.y += S.y; T.z += S.z; T.w += S.w;
            ADD4(aN0, nb4) ADD4(aN1, nb4) ADD4(aN2, nb4) ADD4(aN3, nb4)
            ADD4(aD0, db4) ADD4(aD1, db4) ADD4(aD2, db4) ADD4(aD3, db4)
            #undef ADD4
        }
    }

    const uint4* sA4 = (const uint4*)sAh;
    const uint4* sB4 = (const uint4*)sBh;
    const float4* sW4 = (const float4*)sWf;

    // v init: vqh[s] = half4 (v_b0,v_b1,v_b2,v_b3); LOW writes word0, HIGH word1
    float4 vA, vB;
    {
        int ba = hi ? b2 : b0, bb = hi ? b3 : b1;
        vA = *(const float4*)(state + ba*Un + d0);
        vB = *(const float4*)(state + bb*Un + d0);
        int off = hi ? 1 : 0;
        vqh[2*(d0+0) + off] = packh2(vA.x, vB.x);
        vqh[2*(d0+1) + off] = packh2(vA.y, vB.y);
        vqh[2*(d0+2) + off] = packh2(vA.z, vB.z);
        vqh[2*(d0+3) + off] = packh2(vA.w, vB.w);
    }
    barpair(pid);

    int Lh   = (L + 1) >> 1;
    int eBeg = hi ? Lh : 0;
    int eEnd = hi ? L  : Lh;
    float4* x4 = (float4*)xch;
    const uint2* vq2 = (const uint2*)vqh;

    for (int it = 0; it < NUNF; ++it) {
        mN0 = aN0; mN1 = aN1; mN2 = aN2; mN3 = aN3;
        mD0 = aD0; mD1 = aD1; mD2 = aD2; mD3 = aD3;

        #pragma unroll 4
        for (int e = eBeg; e < eEnd; ++e) {
            uint4 ah = sA4[e*32 + lane];
            uint4 bh = sB4[e*32 + lane];
            float4 we = sW4[e*32 + lane];
            uint2 gx = vq2[widx(we.x)], gy = vq2[widx(we.y)];
            uint2 gz = vq2[widx(we.z)], gw = vq2[widx(we.w)];
            MATHT(ah.x, bh.x, gx, we.x, x)
            MATHT(ah.y, bh.y, gy, we.y, y)
            MATHT(ah.z, bh.z, gz, we.z, z)
            MATHT(ah.w, bh.w, gw, we.w, w)
        }

        // ---- pairwise exchange & update (fp32) ----
        float4 vnA, vnB;
        if (hi) {
            x4[lane]      = mN0;  x4[32 + lane] = mD0;
            x4[64 + lane] = mN1;  x4[96 + lane] = mD1;
        }
        barpair(pid);
        if (!hi) {
            float4 pn0 = x4[lane],      pd0 = x4[32 + lane];
            float4 pn1 = x4[64 + lane], pd1 = x4[96 + lane];
            vnA.x = __fdividef(fmaf(cmt.x, vA.x, mN0.x + pn0.x), mD0.x + pd0.x);
            vnA.y = __fdividef(fmaf(cmt.y, vA.y, mN0.y + pn0.y), mD0.y + pd0.y);
            vnA.z = __fdividef(fmaf(cmt.z, vA.z, mN0.z + pn0.z), mD0.z + pd0.z);
            vnA.w = __fdividef(fmaf(cmt.w, vA.w, mN0.w + pn0.w), mD0.w + pd0.w);
            vnB.x = __fdividef(fmaf(cmt.x, vB.x, mN1.x + pn1.x), mD1.x + pd1.x);
            vnB.y = __fdividef(fmaf(cmt.y, vB.y, mN1.y + pn1.y), mD1.y + pd1.y);
            vnB.z = __fdividef(fmaf(cmt.z, vB.z, mN1.z + pn1.z), mD1.z + pd1.z);
            vnB.w = __fdividef(fmaf(cmt.w, vB.w, mN1.w + pn1.w), mD1.w + pd1.w);
            x4[lane]      = mN2;  x4[32 + lane] = mD2;
            x4[64 + lane] = mN3;  x4[96 + lane] = mD3;
        }
        barpair(pid);
        if (hi) {
            float4 pn2 = x4[lane],      pd2 = x4[32 + lane];
            float4 pn3 = x4[64 + lane], pd3 = x4[96 + lane];
            vnA.x = __fdividef(fmaf(cmt.x, vA.x, mN2.x + pn2.x), mD2.x + pd2.x);
            vnA.y = __fdividef(fmaf(cmt.y, vA.y, mN2.y + pn2.y), mD2.y + pd2.y);
            vnA.z = __fdividef(fmaf(cmt.z, vA.z, mN2.z + pn2.z), mD2.z + pd2.z);
            vnA.w = __fdividef(fmaf(cmt.w, vA.w, mN2.w + pn2.w), mD2.w + pd2.w);
            vnB.x = __fdividef(fmaf(cmt.x, vB.x, mN3.x + pn3.x), mD3.x + pd3.x);
            vnB.y = __fdividef(fmaf(cmt.y, vB.y, mN3.y + pn3.y), mD3.y + pd3.y);
            vnB.z = __fdividef(fmaf(cmt.z, vB.z, mN3.z + pn3.z), mD3.z + pd3.z);
            vnB.w = __fdividef(fmaf(cmt.w, vB.w, mN3.w + pn3.w), mD3.w + pd3.w);
        }
        {   // publish new v halves as fp16 pairs
            int off = hi ? 1 : 0;
            vqh[2*(d0+0) + off] = packh2(vnA.x, vnB.x);
            vqh[2*(d0+1) + off] = packh2(vnA.y, vnB.y);
            vqh[2*(d0+2) + off] = packh2(vnA.z, vnB.z);
            vqh[2*(d0+3) + off] = packh2(vnA.w, vnB.w);
        }
        vA = vnA; vB = vnB;
        barpair(pid);
    }

    // ---- outputs (full fp32 v) ----
    int ba = hi ? b2 : b0, bb = hi ? b3 : b1;
    ((float4*)(dout + Bn*Mn + ba*Un))[lane] = vA;
    ((float4*)(dout + Bn*Mn + bb*Un))[lane] = vB;
    if (d0 < Mn) {
        float4 ow = *(const float4*)(outw + d0);
        float4 ob = *(const float4*)(outb + d0);
        float4 o;
        o.x = fmaf(vA.x, ow.x, ob.x); o.y = fmaf(vA.y, ow.y, ob.y);
        o.z = fmaf(vA.z, ow.z, ob.z); o.w = fmaf(vA.w, ow.w, ob.w);
        ((float4*)(dout + ba*Mn))[lane] = o;
        o.x = fmaf(vB.x, ow.x, ob.x); o.y = fmaf(vB.y, ow.y, ob.y);
        o.z = fmaf(vB.z, ow.z, ob.z); o.w = fmaf(vB.w, ow.w, ob.w);
        ((float4*)(dout + bb*Mn))[lane] = o;
    }
}

extern "C" void kernel_launch(void* const* d_in, const int* in_sizes, int n_in,
                              void* d_out, int out_size) {
    const float* inputs = (const float*)d_in[0];
    const float* state  = (const float*)d_in[1];
    const float* gleak  = (const float*)d_in[2];
    const float* vleak  = (const float*)d_in[3];
    const float* cm     = (const float*)d_in[4];
    const float* sigma  = (const float*)d_in[5];
    const float* mu     = (const float*)d_in[6];
    const float* w      = (const float*)d_in[7];
    const float* erev   = (const float*)d_in[8];
    const float* ssig   = (const float*)d_in[9];
    const float* smu    = (const float*)d_in[10];
    const float* sw     = (const float*)d_in[11];
    const float* serev  = (const float*)d_in[12];
    const float* mask   = (const float*)d_in[13];
    const float* smask  = (const float*)d_in[14];
    const float* inw    = (const float*)d_in[15];
    const float* inb    = (const float*)d_in[16];
    const float* outw   = (const float*)d_in[17];
    const float* outb   = (const float*)d_in[18];
    float* out = (float*)d_out;

    size_t shmem = (size_t)(3*Un*Un + NPAIR*512*2 + 2*Un + 2) * sizeof(float);  // ~226 KB
    cudaFuncSetAttribute(ltc_all, cudaFuncAttributeMaxDynamicSharedMemorySize, (int)shmem);
    ltc_all<<<148, NTHR, shmem>>>(inputs, state, gleak, vleak, cm,
                                  sigma, mu, w, erev, ssig, smu, sw, serev,
                                  mask, smask, inw, inb, outw, outb, out);
}